// round 13
// baseline (speedup 1.0000x reference)
#include <cuda_runtime.h>
#include <stdint.h>

// out[b][r] = prod_i v(b,i,mf[r][i]) = exp2( sum_k S[r,k] * L[b,k] )
//   L[b,k] = clamp(log2(x[b,k&31]), -126) split into bf16 hi (k<32) / lo (k>=32)
//   S[r,k] = one-hot (0/1), duplicated hi|lo -> exact select, K=64
// mma.sync m16n8k16 bf16 (compute_103-safe; tcgen05 blocked by toolchain).
// M=rules, N=batches. A(one-hot) in registers; B(L) in smem via ldmatrix
// (rows padded to 144B -> conflict-free LDSM). Epilogue: ex2 -> per-warp
// XOR-swizzled smem stage (conflict-free both directions) -> coalesced STG.
// Persistent 148 CTAs x 512 thr; tile 128x128; double-buffered L; 1 bar/tile.

#define THREADS 512
#define NSM 148
#define LROW 144                     // bytes per L row (64 bf16 + 8 pad)
#define LBUF (128 * LROW)            // 18432
#define STAGE_OFF (2 * LBUF)         // 36864
#define SMEM_TOTAL (STAGE_OFF + 16 * 4096)   // 102400

__device__ __forceinline__ uint32_t smem_u32(const void* p) {
    uint32_t a;
    asm("{ .reg .u64 t; cvta.to.shared.u64 t, %1; cvt.u32.u64 %0, t; }"
        : "=r"(a) : "l"(p));
    return a;
}
__device__ __forceinline__ uint32_t bf16rn(float f) {
    uint32_t u = __float_as_uint(f);
    return (u + 0x7FFFu + ((u >> 16) & 1u)) >> 16;
}
__device__ __forceinline__ float lg2c(float f) {
    float r;
    asm("lg2.approx.f32 %0, %1;" : "=f"(r) : "f"(f));
    return fmaxf(r, -126.0f);
}
__device__ __forceinline__ float ex2f(float f) {
    float r;
    asm("ex2.approx.f32 %0, %1;" : "=f"(r) : "f"(f));
    return r;
}
// one-hot bf16x2 for cols (k, k+1); k even, both in same input group
__device__ __forceinline__ uint32_t pack2(const int* id, int k) {
    int kk = k & 31, i = kk >> 2, m = kk & 3;
    uint32_t a = (id[i] == m)     ? 0x3F80u : 0u;
    uint32_t b = (id[i] == m + 1) ? 0x3F80u : 0u;
    return a | (b << 16);
}

__global__ __launch_bounds__(THREADS, 1)
void fire_kernel(const float* __restrict__ x, const int* __restrict__ mf,
                 float* __restrict__ out, int n_rules, int ntiles, int nbt) {
    extern __shared__ char sm[];
    const uint32_t smb = smem_u32(sm);
    const int tid  = threadIdx.x;
    const int lane = tid & 31;
    const int wid  = tid >> 5;
    const int wm   = wid >> 2;         // warp m-block (32 rules)
    const int wn   = wid & 3;          // warp n-block (32 batches)
    const int q    = lane & 3;         // col quad
    const int lh   = lane >> 2;        // row-in-8

    // L build mapping: thread -> (batch row, 8-col group)
    const int bb = tid >> 2;
    const int bc = (tid & 3) * 8;

    float* stg = (float*)(sm + STAGE_OFF + wid * 4096);
    int par = 0;

    for (int t = blockIdx.x; t < ntiles; t += NSM) {
        const int rt = t / nbt;
        const int bt = t - rt * nbt;
        const int r0 = rt << 7;
        const int b0 = bt << 7;
        char* Lbase = sm + par * LBUF;

        // ---- build L (hi|lo bf16) for 128 batches ----
        {
            const float* xp = x + (size_t)(b0 + bb) * 32 + bc;
            float4 v0 = *(const float4*)xp;
            float4 v1 = *(const float4*)(xp + 4);
            float vv[8] = {v0.x, v0.y, v0.z, v0.w, v1.x, v1.y, v1.z, v1.w};
            uint32_t H[4] = {0, 0, 0, 0}, Lo[4] = {0, 0, 0, 0};
#pragma unroll
            for (int e = 0; e < 8; ++e) {
                float lg = lg2c(vv[e]);
                uint32_t h = bf16rn(lg);
                float hf = __uint_as_float(h << 16);
                uint32_t l = bf16rn(lg - hf);
                H[e >> 1]  |= h << (16 * (e & 1));
                Lo[e >> 1] |= l << (16 * (e & 1));
            }
            char* row = Lbase + bb * LROW;
            *(uint4*)(row + bc * 2)      = make_uint4(H[0], H[1], H[2], H[3]);
            *(uint4*)(row + 64 + bc * 2) = make_uint4(Lo[0], Lo[1], Lo[2], Lo[3]);
        }

        // ---- rebuild A (one-hot) registers for this rule tile ----
        uint32_t A[2][4][4];
#pragma unroll
        for (int j = 0; j < 4; ++j) {
            const int4* mp = (const int4*)(mf + (size_t)(r0 + 32 * wm + lh + 8 * j) * 8);
            int4 u = mp[0], w = mp[1];
            int id[8] = {u.x, u.y, u.z, u.w, w.x, w.y, w.z, w.w};
            const int s = j >> 1, rr = j & 1;
#pragma unroll
            for (int kt = 0; kt < 4; ++kt) {
                int kb = 16 * kt + 2 * q;
                A[s][kt][rr]     = pack2(id, kb);
                A[s][kt][rr + 2] = pack2(id, kb + 8);
            }
        }

        __syncthreads();   // L visible before ldmatrix; also fences prev tile's reads

        // ---- MMA mainloop: warp computes 32 rules x 32 batches, K=64 ----
        float C[2][4][4];
#pragma unroll
        for (int s = 0; s < 2; ++s)
#pragma unroll
            for (int nt = 0; nt < 4; ++nt)
#pragma unroll
                for (int c = 0; c < 4; ++c) C[s][nt][c] = 0.0f;

        const uint32_t lmb = smb + par * LBUF
                           + (uint32_t)(32 * wn + (lane & 7)) * LROW
                           + (uint32_t)(lane >> 3) * 16;
#pragma unroll
        for (int t2 = 0; t2 < 2; ++t2) {
#pragma unroll
            for (int nt = 0; nt < 4; ++nt) {
                uint32_t B0, B1, B2, B3;
                asm volatile(
                    "ldmatrix.sync.aligned.m8n8.x4.shared.b16 {%0,%1,%2,%3}, [%4];"
                    : "=r"(B0), "=r"(B1), "=r"(B2), "=r"(B3)
                    : "r"(lmb + (uint32_t)(nt * 8 * LROW + t2 * 64)));
#pragma unroll
                for (int s = 0; s < 2; ++s) {
                    asm volatile(
                        "mma.sync.aligned.m16n8k16.row.col.f32.bf16.bf16.f32 "
                        "{%0,%1,%2,%3}, {%4,%5,%6,%7}, {%8,%9}, {%0,%1,%2,%3};"
                        : "+f"(C[s][nt][0]), "+f"(C[s][nt][1]),
                          "+f"(C[s][nt][2]), "+f"(C[s][nt][3])
                        : "r"(A[s][2 * t2][0]), "r"(A[s][2 * t2][1]),
                          "r"(A[s][2 * t2][2]), "r"(A[s][2 * t2][3]),
                          "r"(B0), "r"(B1));
                    asm volatile(
                        "mma.sync.aligned.m16n8k16.row.col.f32.bf16.bf16.f32 "
                        "{%0,%1,%2,%3}, {%4,%5,%6,%7}, {%8,%9}, {%0,%1,%2,%3};"
                        : "+f"(C[s][nt][0]), "+f"(C[s][nt][1]),
                          "+f"(C[s][nt][2]), "+f"(C[s][nt][3])
                        : "r"(A[s][2 * t2 + 1][0]), "r"(A[s][2 * t2 + 1][1]),
                          "r"(A[s][2 * t2 + 1][2]), "r"(A[s][2 * t2 + 1][3]),
                          "r"(B2), "r"(B3));
                }
            }
        }

        // ---- epilogue: ex2 -> swizzled per-warp stage -> coalesced STG ----
#pragma unroll
        for (int s = 0; s < 2; ++s)
#pragma unroll
            for (int nt = 0; nt < 4; ++nt)
#pragma unroll
                for (int c = 0; c < 4; ++c) {
                    int rl = 16 * s + lh + 8 * (c >> 1);
                    int bl = 8 * nt + 2 * q + (c & 1);
                    stg[bl * 32 + (rl ^ ((bl & 6) << 2))] = ex2f(C[s][nt][c]);
                }
        __syncwarp();

        {
            float* ob = out + (size_t)(b0 + 32 * wn) * n_rules + r0 + 32 * wm + lane;
#pragma unroll 4
            for (int b = 0; b < 32; ++b) {
                ob[(size_t)b * n_rules] = stg[b * 32 + (lane ^ ((b & 6) << 2))];
            }
        }
        __syncwarp();
        par ^= 1;
    }
}

extern "C" void kernel_launch(void* const* d_in, const int* in_sizes, int n_in,
                              void* d_out, int out_size) {
    const float* x  = (const float*)d_in[0];
    const int*   mf = (const int*)d_in[1];
    float* out = (float*)d_out;

    const int n_rules = in_sizes[1] / 8;      // 2048
    const int B       = in_sizes[0] / 32;     // 8192
    const int nrt     = n_rules >> 7;         // 16
    const int nbt     = B >> 7;               // 64
    const int ntiles  = nrt * nbt;            // 1024

    cudaFuncSetAttribute(fire_kernel, cudaFuncAttributeMaxDynamicSharedMemorySize, SMEM_TOTAL);
    fire_kernel<<<NSM, THREADS, SMEM_TOTAL>>>(x, mf, out, n_rules, ntiles, nbt);
}

// round 14
// speedup vs baseline: 1.1587x; 1.1587x over previous
#include <cuda_runtime.h>
#include <stdint.h>

// out[b][r] = prod_i v(b,i,mf[r][i]) = exp2( sum_k S[r,k] * L[b,k] )
//   L[b,k] = clamp(log2(x[b,k&31]), -126), bf16 hi (k<32) / lo (k>=32) split
//   S[r,k] = one-hot (0/1) duplicated hi|lo -> exact select, K=64
// mma.sync m16n8k16 bf16. M=rules, N=batches.
// R14: A(one-hot) built ONCE per CTA (grid = 16 rule tiles x 8 batch
// streams = 128 CTAs, 8 contiguous batch tiles each, perfectly balanced);
// epilogue staging uses padded stride-36 layout (bijective mod 32 on both
// write and read) -> pure-IMAD indexing, conflict-free.

#define THREADS 512
#define NBLK 128
#define LROW 144                     // bytes per L row (64 bf16 + 8 pad)
#define LBUF (128 * LROW)            // 18432
#define STAGE_OFF (2 * LBUF)         // 36864
#define STG_STRIDE 36                // floats per staged batch row
#define STAGE_WARP (32 * STG_STRIDE) // 1152 floats per warp
#define SMEM_TOTAL (STAGE_OFF + 16 * STAGE_WARP * 4)   // 110592

__device__ __forceinline__ uint32_t smem_u32(const void* p) {
    uint32_t a;
    asm("{ .reg .u64 t; cvta.to.shared.u64 t, %1; cvt.u32.u64 %0, t; }"
        : "=r"(a) : "l"(p));
    return a;
}
__device__ __forceinline__ uint32_t bf16rn(float f) {
    uint32_t u = __float_as_uint(f);
    return (u + 0x7FFFu + ((u >> 16) & 1u)) >> 16;
}
__device__ __forceinline__ float lg2c(float f) {
    float r;
    asm("lg2.approx.f32 %0, %1;" : "=f"(r) : "f"(f));
    return fmaxf(r, -126.0f);
}
__device__ __forceinline__ float ex2f(float f) {
    float r;
    asm("ex2.approx.f32 %0, %1;" : "=f"(r) : "f"(f));
    return r;
}
__device__ __forceinline__ uint32_t pack2(const int* id, int k) {
    int kk = k & 31, i = kk >> 2, m = kk & 3;
    uint32_t a = (id[i] == m)     ? 0x3F80u : 0u;
    uint32_t b = (id[i] == m + 1) ? 0x3F80u : 0u;
    return a | (b << 16);
}

__global__ __launch_bounds__(THREADS, 1)
void fire_kernel(const float* __restrict__ x, const int* __restrict__ mf,
                 float* __restrict__ out, int n_rules) {
    extern __shared__ char sm[];
    const uint32_t smb = smem_u32(sm);
    const int tid  = threadIdx.x;
    const int lane = tid & 31;
    const int wid  = tid >> 5;
    const int wm   = wid >> 2;         // warp m-block (32 rules)
    const int wn   = wid & 3;          // warp n-block (32 batches)
    const int q    = lane & 3;
    const int lh   = lane >> 2;

    const int rt     = (int)blockIdx.x & 15;      // fixed rule tile
    const int stream = (int)blockIdx.x >> 4;      // 8 streams
    const int r0     = rt << 7;

    // L build mapping: thread -> (batch row, 8-col group)
    const int bb = tid >> 2;
    const int bc = (tid & 3) * 8;

    float* stg = (float*)(sm + STAGE_OFF) + wid * STAGE_WARP;

    // ---- build A (one-hot) ONCE for this CTA's rule tile ----
    uint32_t A[2][4][4];
#pragma unroll
    for (int j = 0; j < 4; ++j) {
        const int4* mp = (const int4*)(mf + (size_t)(r0 + 32 * wm + lh + 8 * j) * 8);
        int4 u = mp[0], w = mp[1];
        int id[8] = {u.x, u.y, u.z, u.w, w.x, w.y, w.z, w.w};
        const int s = j >> 1, rr = j & 1;
#pragma unroll
        for (int kt = 0; kt < 4; ++kt) {
            int kb = 16 * kt + 2 * q;
            A[s][kt][rr]     = pack2(id, kb);
            A[s][kt][rr + 2] = pack2(id, kb + 8);
        }
    }

    int par = 0;
#pragma unroll 1
    for (int it = 0; it < 8; ++it) {
        const int b0 = (stream * 8 + it) << 7;
        char* Lbase = sm + par * LBUF;

        // ---- build L (hi|lo bf16) for 128 batches ----
        {
            const float* xp = x + (size_t)(b0 + bb) * 32 + bc;
            float4 v0 = *(const float4*)xp;
            float4 v1 = *(const float4*)(xp + 4);
            float vv[8] = {v0.x, v0.y, v0.z, v0.w, v1.x, v1.y, v1.z, v1.w};
            uint32_t H[4] = {0, 0, 0, 0}, Lo[4] = {0, 0, 0, 0};
#pragma unroll
            for (int e = 0; e < 8; ++e) {
                float lg = lg2c(vv[e]);
                uint32_t h = bf16rn(lg);
                float hf = __uint_as_float(h << 16);
                uint32_t l = bf16rn(lg - hf);
                H[e >> 1]  |= h << (16 * (e & 1));
                Lo[e >> 1] |= l << (16 * (e & 1));
            }
            char* row = Lbase + bb * LROW;
            *(uint4*)(row + bc * 2)      = make_uint4(H[0], H[1], H[2], H[3]);
            *(uint4*)(row + 64 + bc * 2) = make_uint4(Lo[0], Lo[1], Lo[2], Lo[3]);
        }

        __syncthreads();   // L visible; also orders prev tile's LDSM reads

        // ---- MMA: warp computes 32 rules x 32 batches, K=64 ----
        float C[2][4][4];
#pragma unroll
        for (int s = 0; s < 2; ++s)
#pragma unroll
            for (int nt = 0; nt < 4; ++nt)
#pragma unroll
                for (int c = 0; c < 4; ++c) C[s][nt][c] = 0.0f;

        const uint32_t lmb = smb + par * LBUF
                           + (uint32_t)(32 * wn + (lane & 7)) * LROW
                           + (uint32_t)(lane >> 3) * 16;
#pragma unroll
        for (int t2 = 0; t2 < 2; ++t2) {
#pragma unroll
            for (int nt = 0; nt < 4; ++nt) {
                uint32_t B0, B1, B2, B3;
                asm volatile(
                    "ldmatrix.sync.aligned.m8n8.x4.shared.b16 {%0,%1,%2,%3}, [%4];"
                    : "=r"(B0), "=r"(B1), "=r"(B2), "=r"(B3)
                    : "r"(lmb + (uint32_t)(nt * 8 * LROW + t2 * 64)));
#pragma unroll
                for (int s = 0; s < 2; ++s) {
                    asm volatile(
                        "mma.sync.aligned.m16n8k16.row.col.f32.bf16.bf16.f32 "
                        "{%0,%1,%2,%3}, {%4,%5,%6,%7}, {%8,%9}, {%0,%1,%2,%3};"
                        : "+f"(C[s][nt][0]), "+f"(C[s][nt][1]),
                          "+f"(C[s][nt][2]), "+f"(C[s][nt][3])
                        : "r"(A[s][2 * t2][0]), "r"(A[s][2 * t2][1]),
                          "r"(A[s][2 * t2][2]), "r"(A[s][2 * t2][3]),
                          "r"(B0), "r"(B1));
                    asm volatile(
                        "mma.sync.aligned.m16n8k16.row.col.f32.bf16.bf16.f32 "
                        "{%0,%1,%2,%3}, {%4,%5,%6,%7}, {%8,%9}, {%0,%1,%2,%3};"
                        : "+f"(C[s][nt][0]), "+f"(C[s][nt][1]),
                          "+f"(C[s][nt][2]), "+f"(C[s][nt][3])
                        : "r"(A[s][2 * t2 + 1][0]), "r"(A[s][2 * t2 + 1][1]),
                          "r"(A[s][2 * t2 + 1][2]), "r"(A[s][2 * t2 + 1][3]),
                          "r"(B2), "r"(B3));
                }
            }
        }

        // ---- epilogue: ex2 -> stride-36 staged (bijective mod 32) -> STG ----
        {
            float* sw = stg + 2 * q * STG_STRIDE + lh;  // (bl=2q+..)*36 + rl base
#pragma unroll
            for (int s = 0; s < 2; ++s)
#pragma unroll
                for (int nt = 0; nt < 4; ++nt)
#pragma unroll
                    for (int c = 0; c < 4; ++c) {
                        // bl = 8nt+2q+(c&1); rl = 16s+lh+8(c>>1)
                        sw[(8 * nt + (c & 1)) * STG_STRIDE + 16 * s + 8 * (c >> 1)]
                            = ex2f(C[s][nt][c]);
                    }
        }
        __syncwarp();
        {
            float* ob = out + (size_t)(b0 + 32 * wn) * n_rules + r0 + 32 * wm + lane;
            const float* sr = stg + lane;
#pragma unroll 4
            for (int b = 0; b < 32; ++b) {
                ob[(size_t)b * n_rules] = sr[b * STG_STRIDE];
            }
        }
        __syncwarp();
        par ^= 1;
    }
}

extern "C" void kernel_launch(void* const* d_in, const int* in_sizes, int n_in,
                              void* d_out, int out_size) {
    const float* x  = (const float*)d_in[0];
    const int*   mf = (const int*)d_in[1];
    float* out = (float*)d_out;

    const int n_rules = in_sizes[1] / 8;      // 2048

    cudaFuncSetAttribute(fire_kernel, cudaFuncAttributeMaxDynamicSharedMemorySize, SMEM_TOTAL);
    fire_kernel<<<NBLK, THREADS, SMEM_TOTAL>>>(x, mf, out, n_rules);
}

// round 15
// speedup vs baseline: 1.2312x; 1.0626x over previous
#include <cuda_runtime.h>
#include <stdint.h>

// out[b][r] = prod_i v(b,i,mf[r][i]) = exp2( sum_k S[r,k] * L[b,k] )
//   L[b,k] = clamp(log2(x[b,k&31]), -126), bf16 hi (k<32) / lo (k>=32) split
//   S[r,k] = one-hot (0/1) duplicated hi|lo -> exact select, K=64
// mma.sync m16n8k16 bf16. M=rules, N=batches.
// R15: occupancy fix. Warp tile 32x16 (C=16 regs) -> ~60 live regs ->
// __launch_bounds__(512,2) = 32 warps/SM. CTA tile 128 rules x 64 batches;
// grid 256 = 16 rule tiles x 16 streams (8 batch tiles each, balanced);
// all 148 SMs busy. A one-hot built once per CTA. Double-buffered L,
// one __syncthreads per tile. Stride-36 staged epilogue (conflict-free).

#define THREADS 512
#define NBLK 256
#define LROW 144                       // bytes per L row (64 bf16 + 8 pad)
#define LBUF (64 * LROW)               // 9216 (64 batches)
#define STAGE_OFF (2 * LBUF)           // 18432
#define STG_STRIDE 36
#define STAGE_WARP (16 * STG_STRIDE)   // 576 floats per warp
#define SMEM_TOTAL (STAGE_OFF + 16 * STAGE_WARP * 4)   // 55296

__device__ __forceinline__ uint32_t smem_u32(const void* p) {
    uint32_t a;
    asm("{ .reg .u64 t; cvta.to.shared.u64 t, %1; cvt.u32.u64 %0, t; }"
        : "=r"(a) : "l"(p));
    return a;
}
__device__ __forceinline__ uint32_t bf16rn(float f) {
    uint32_t u = __float_as_uint(f);
    return (u + 0x7FFFu + ((u >> 16) & 1u)) >> 16;
}
__device__ __forceinline__ float lg2c(float f) {
    float r;
    asm("lg2.approx.f32 %0, %1;" : "=f"(r) : "f"(f));
    return fmaxf(r, -126.0f);
}
__device__ __forceinline__ float ex2f(float f) {
    float r;
    asm("ex2.approx.f32 %0, %1;" : "=f"(r) : "f"(f));
    return r;
}
__device__ __forceinline__ uint32_t pack2(const int* id, int k) {
    int kk = k & 31, i = kk >> 2, m = kk & 3;
    uint32_t a = (id[i] == m)     ? 0x3F80u : 0u;
    uint32_t b = (id[i] == m + 1) ? 0x3F80u : 0u;
    return a | (b << 16);
}

__global__ __launch_bounds__(THREADS, 2)
void fire_kernel(const float* __restrict__ x, const int* __restrict__ mf,
                 float* __restrict__ out, int n_rules) {
    extern __shared__ char sm[];
    const uint32_t smb = smem_u32(sm);
    const int tid  = threadIdx.x;
    const int lane = tid & 31;
    const int wid  = tid >> 5;
    const int wm   = wid >> 2;         // warp m-block (32 rules)
    const int wn   = wid & 3;          // warp n-block (16 batches)
    const int q    = lane & 3;
    const int lh   = lane >> 2;

    const int rt     = (int)blockIdx.x & 15;      // fixed rule tile
    const int stream = (int)blockIdx.x >> 4;      // 16 streams
    const int r0     = rt << 7;

    // L build mapping: threads 0..255 -> (batch row 0..63, 8-col group)
    const int bb = tid >> 2;
    const int bc = (tid & 3) * 8;

    float* stg = (float*)(sm + STAGE_OFF) + wid * STAGE_WARP;

    // ---- build A (one-hot) ONCE for this CTA's rule tile ----
    uint32_t A[2][4][4];
#pragma unroll
    for (int j = 0; j < 4; ++j) {
        const int4* mp = (const int4*)(mf + (size_t)(r0 + 32 * wm + lh + 8 * j) * 8);
        int4 u = mp[0], w = mp[1];
        int id[8] = {u.x, u.y, u.z, u.w, w.x, w.y, w.z, w.w};
        const int s = j >> 1, rr = j & 1;
#pragma unroll
        for (int kt = 0; kt < 4; ++kt) {
            int kb = 16 * kt + 2 * q;
            A[s][kt][rr]     = pack2(id, kb);
            A[s][kt][rr + 2] = pack2(id, kb + 8);
        }
    }

    int par = 0;
#pragma unroll 1
    for (int it = 0; it < 8; ++it) {
        const int b0 = (stream * 8 + it) << 6;    // 64-batch tiles
        char* Lbase = sm + par * LBUF;

        // ---- build L (hi|lo bf16) for 64 batches (threads 0..255) ----
        if (tid < 256) {
            const float* xp = x + (size_t)(b0 + bb) * 32 + bc;
            float4 v0 = *(const float4*)xp;
            float4 v1 = *(const float4*)(xp + 4);
            float vv[8] = {v0.x, v0.y, v0.z, v0.w, v1.x, v1.y, v1.z, v1.w};
            uint32_t H[4] = {0, 0, 0, 0}, Lo[4] = {0, 0, 0, 0};
#pragma unroll
            for (int e = 0; e < 8; ++e) {
                float lg = lg2c(vv[e]);
                uint32_t h = bf16rn(lg);
                float hf = __uint_as_float(h << 16);
                uint32_t l = bf16rn(lg - hf);
                H[e >> 1]  |= h << (16 * (e & 1));
                Lo[e >> 1] |= l << (16 * (e & 1));
            }
            char* row = Lbase + bb * LROW;
            *(uint4*)(row + bc * 2)      = make_uint4(H[0], H[1], H[2], H[3]);
            *(uint4*)(row + 64 + bc * 2) = make_uint4(Lo[0], Lo[1], Lo[2], Lo[3]);
        }

        __syncthreads();   // L visible; also orders prev tile's LDSM reads

        // ---- MMA: warp computes 32 rules x 16 batches, K=64 ----
        float C[2][2][4];
#pragma unroll
        for (int s = 0; s < 2; ++s)
#pragma unroll
            for (int nt = 0; nt < 2; ++nt)
#pragma unroll
                for (int c = 0; c < 4; ++c) C[s][nt][c] = 0.0f;

        const uint32_t lmb = smb + par * LBUF
                           + (uint32_t)(16 * wn + (lane & 7)) * LROW
                           + (uint32_t)(lane >> 3) * 16;
#pragma unroll
        for (int t2 = 0; t2 < 2; ++t2) {
#pragma unroll
            for (int nt = 0; nt < 2; ++nt) {
                uint32_t B0, B1, B2, B3;
                asm volatile(
                    "ldmatrix.sync.aligned.m8n8.x4.shared.b16 {%0,%1,%2,%3}, [%4];"
                    : "=r"(B0), "=r"(B1), "=r"(B2), "=r"(B3)
                    : "r"(lmb + (uint32_t)(nt * 8 * LROW + t2 * 64)));
#pragma unroll
                for (int s = 0; s < 2; ++s) {
                    asm volatile(
                        "mma.sync.aligned.m16n8k16.row.col.f32.bf16.bf16.f32 "
                        "{%0,%1,%2,%3}, {%4,%5,%6,%7}, {%8,%9}, {%0,%1,%2,%3};"
                        : "+f"(C[s][nt][0]), "+f"(C[s][nt][1]),
                          "+f"(C[s][nt][2]), "+f"(C[s][nt][3])
                        : "r"(A[s][2 * t2][0]), "r"(A[s][2 * t2][1]),
                          "r"(A[s][2 * t2][2]), "r"(A[s][2 * t2][3]),
                          "r"(B0), "r"(B1));
                    asm volatile(
                        "mma.sync.aligned.m16n8k16.row.col.f32.bf16.bf16.f32 "
                        "{%0,%1,%2,%3}, {%4,%5,%6,%7}, {%8,%9}, {%0,%1,%2,%3};"
                        : "+f"(C[s][nt][0]), "+f"(C[s][nt][1]),
                          "+f"(C[s][nt][2]), "+f"(C[s][nt][3])
                        : "r"(A[s][2 * t2 + 1][0]), "r"(A[s][2 * t2 + 1][1]),
                          "r"(A[s][2 * t2 + 1][2]), "r"(A[s][2 * t2 + 1][3]),
                          "r"(B2), "r"(B3));
                }
            }
        }

        // ---- epilogue: ex2 -> stride-36 staged (conflict-free) -> STG ----
        {
            float* sw = stg + 2 * q * STG_STRIDE + lh;
#pragma unroll
            for (int s = 0; s < 2; ++s)
#pragma unroll
                for (int nt = 0; nt < 2; ++nt)
#pragma unroll
                    for (int c = 0; c < 4; ++c) {
                        // bl = 8nt+2q+(c&1); rl = 16s+lh+8(c>>1)
                        sw[(8 * nt + (c & 1)) * STG_STRIDE + 16 * s + 8 * (c >> 1)]
                            = ex2f(C[s][nt][c]);
                    }
        }
        __syncwarp();
        {
            float* ob = out + (size_t)(b0 + 16 * wn) * n_rules + r0 + 32 * wm + lane;
            const float* sr = stg + lane;
#pragma unroll 4
            for (int b = 0; b < 16; ++b) {
                ob[(size_t)b * n_rules] = sr[b * STG_STRIDE];
            }
        }
        __syncwarp();
        par ^= 1;
    }
}

extern "C" void kernel_launch(void* const* d_in, const int* in_sizes, int n_in,
                              void* d_out, int out_size) {
    const float* x  = (const float*)d_in[0];
    const int*   mf = (const int*)d_in[1];
    float* out = (float*)d_out;

    const int n_rules = in_sizes[1] / 8;      // 2048

    cudaFuncSetAttribute(fire_kernel, cudaFuncAttributeMaxDynamicSharedMemorySize, SMEM_TOTAL);
    fire_kernel<<<NBLK, THREADS, SMEM_TOTAL>>>(x, mf, out, n_rules);
}

// round 17
// speedup vs baseline: 1.4718x; 1.1954x over previous
#include <cuda_runtime.h>
#include <stdint.h>

// out[b][r] = prod_i v(b,i,mf[r][i]) = exp2( sum_k S[r,k] * L[b,k] )
//   L: clamp(log2 x, -126) split bf16 hi/lo (K=64), S: one-hot 0/1 -> exact.
// mma.sync m16n8k16 bf16; M=rules, N=batches.
// R17 = R16 with the coverage bug fixed: there are 128 batch tiles
// (B=8192, 64 per tile), not 64. Grid 296 (2 CTAs/SM everywhere);
// build of tile j+1 into alternate L buffer before computing tile j.

#define THREADS 512
#define NBLK 296
#define NBT 128                        // batch tiles (8192/64)
#define LROW 144                       // bytes per L row (64 bf16 + 8 pad)
#define LBUF (64 * LROW)               // 9216
#define STAGE_OFF (2 * LBUF)           // 18432
#define STG_STRIDE 36
#define STAGE_WARP (16 * STG_STRIDE)   // 576 floats per warp
#define SMEM_TOTAL (STAGE_OFF + 16 * STAGE_WARP * 4)   // 55296

__device__ __forceinline__ uint32_t smem_u32(const void* p) {
    uint32_t a;
    asm("{ .reg .u64 t; cvta.to.shared.u64 t, %1; cvt.u32.u64 %0, t; }"
        : "=r"(a) : "l"(p));
    return a;
}
__device__ __forceinline__ uint32_t bf16rn(float f) {
    uint32_t u = __float_as_uint(f);
    return (u + 0x7FFFu + ((u >> 16) & 1u)) >> 16;
}
__device__ __forceinline__ float lg2c(float f) {
    float r;
    asm("lg2.approx.f32 %0, %1;" : "=f"(r) : "f"(f));
    return fmaxf(r, -126.0f);
}
__device__ __forceinline__ float ex2f(float f) {
    float r;
    asm("ex2.approx.f32 %0, %1;" : "=f"(r) : "f"(f));
    return r;
}
__device__ __forceinline__ uint32_t pack2(const int* id, int k) {
    int kk = k & 31, i = kk >> 2, m = kk & 3;
    uint32_t a = (id[i] == m)     ? 0x3F80u : 0u;
    uint32_t b = (id[i] == m + 1) ? 0x3F80u : 0u;
    return a | (b << 16);
}

__global__ __launch_bounds__(THREADS, 2)
void fire_kernel(const float* __restrict__ x, const int* __restrict__ mf,
                 float* __restrict__ out, int n_rules) {
    extern __shared__ char sm[];
    const uint32_t smb = smem_u32(sm);
    const int tid  = threadIdx.x;
    const int lane = tid & 31;
    const int wid  = tid >> 5;
    const int wm   = wid >> 2;
    const int wn   = wid & 3;
    const int q    = lane & 3;
    const int lh   = lane >> 2;

    const int rt     = (int)blockIdx.x & 15;
    const int stream = (int)blockIdx.x >> 4;          // rt<8: 0..18, rt>=8: 0..17
    const int nstr   = (rt < 8) ? 19 : 18;
    const int r0     = rt << 7;

    // L build mapping (threads 0..255): batch row, 8-col group
    const int bbr = tid >> 2;
    const int bcc = (tid & 3) * 8;

    float* stg = (float*)(sm + STAGE_OFF) + wid * STAGE_WARP;

    // ---- build A (one-hot) once for this CTA's rule tile ----
    uint32_t A[2][4][4];
#pragma unroll
    for (int j = 0; j < 4; ++j) {
        const int4* mp = (const int4*)(mf + (size_t)(r0 + 32 * wm + lh + 8 * j) * 8);
        int4 u = mp[0], w = mp[1];
        int id[8] = {u.x, u.y, u.z, u.w, w.x, w.y, w.z, w.w};
        const int s = j >> 1, rr = j & 1;
#pragma unroll
        for (int kt = 0; kt < 4; ++kt) {
            int kb = 16 * kt + 2 * q;
            A[s][kt][rr]     = pack2(id, kb);
            A[s][kt][rr + 2] = pack2(id, kb + 8);
        }
    }

    auto buildL = [&](int bt, int buf) {
        if (tid >= 256) return;
        const float* xp = x + (((size_t)bt << 6) + bbr) * 32 + bcc;
        float4 v0 = *(const float4*)xp;
        float4 v1 = *(const float4*)(xp + 4);
        float vv[8] = {v0.x, v0.y, v0.z, v0.w, v1.x, v1.y, v1.z, v1.w};
        uint32_t H[4] = {0, 0, 0, 0}, Lo[4] = {0, 0, 0, 0};
#pragma unroll
        for (int e = 0; e < 8; ++e) {
            float lg = lg2c(vv[e]);
            uint32_t h = bf16rn(lg);
            float hf = __uint_as_float(h << 16);
            uint32_t l = bf16rn(lg - hf);
            H[e >> 1]  |= h << (16 * (e & 1));
            Lo[e >> 1] |= l << (16 * (e & 1));
        }
        char* row = sm + buf * LBUF + bbr * LROW;
        *(uint4*)(row + bcc * 2)      = make_uint4(H[0], H[1], H[2], H[3]);
        *(uint4*)(row + 64 + bcc * 2) = make_uint4(Lo[0], Lo[1], Lo[2], Lo[3]);
    };

    int bt = stream;
    buildL(bt, 0);
    __syncthreads();

    int par = 0;
#pragma unroll 1
    for (; bt < NBT; bt += nstr) {
        // issue NEXT tile's build into the alternate buffer first
        if (bt + nstr < NBT) buildL(bt + nstr, par ^ 1);

        const int b0 = bt << 6;

        // ---- MMA: 32 rules x 16 batches per warp, K=64 ----
        float C[2][2][4];
#pragma unroll
        for (int s = 0; s < 2; ++s)
#pragma unroll
            for (int nt = 0; nt < 2; ++nt)
#pragma unroll
                for (int c = 0; c < 4; ++c) C[s][nt][c] = 0.0f;

        const uint32_t lmb = smb + par * LBUF
                           + (uint32_t)(16 * wn + (lane & 7)) * LROW
                           + (uint32_t)(lane >> 3) * 16;
#pragma unroll
        for (int t2 = 0; t2 < 2; ++t2) {
#pragma unroll
            for (int nt = 0; nt < 2; ++nt) {
                uint32_t B0, B1, B2, B3;
                asm volatile(
                    "ldmatrix.sync.aligned.m8n8.x4.shared.b16 {%0,%1,%2,%3}, [%4];"
                    : "=r"(B0), "=r"(B1), "=r"(B2), "=r"(B3)
                    : "r"(lmb + (uint32_t)(nt * 8 * LROW + t2 * 64)));
#pragma unroll
                for (int s = 0; s < 2; ++s) {
                    asm volatile(
                        "mma.sync.aligned.m16n8k16.row.col.f32.bf16.bf16.f32 "
                        "{%0,%1,%2,%3}, {%4,%5,%6,%7}, {%8,%9}, {%0,%1,%2,%3};"
                        : "+f"(C[s][nt][0]), "+f"(C[s][nt][1]),
                          "+f"(C[s][nt][2]), "+f"(C[s][nt][3])
                        : "r"(A[s][2 * t2][0]), "r"(A[s][2 * t2][1]),
                          "r"(A[s][2 * t2][2]), "r"(A[s][2 * t2][3]),
                          "r"(B0), "r"(B1));
                    asm volatile(
                        "mma.sync.aligned.m16n8k16.row.col.f32.bf16.bf16.f32 "
                        "{%0,%1,%2,%3}, {%4,%5,%6,%7}, {%8,%9}, {%0,%1,%2,%3};"
                        : "+f"(C[s][nt][0]), "+f"(C[s][nt][1]),
                          "+f"(C[s][nt][2]), "+f"(C[s][nt][3])
                        : "r"(A[s][2 * t2 + 1][0]), "r"(A[s][2 * t2 + 1][1]),
                          "r"(A[s][2 * t2 + 1][2]), "r"(A[s][2 * t2 + 1][3]),
                          "r"(B2), "r"(B3));
                }
            }
        }

        // ---- epilogue: ex2 -> stride-36 stage (conflict-free) -> STG ----
        {
            float* sw = stg + 2 * q * STG_STRIDE + lh;
#pragma unroll
            for (int s = 0; s < 2; ++s)
#pragma unroll
                for (int nt = 0; nt < 2; ++nt)
#pragma unroll
                    for (int c = 0; c < 4; ++c) {
                        sw[(8 * nt + (c & 1)) * STG_STRIDE + 16 * s + 8 * (c >> 1)]
                            = ex2f(C[s][nt][c]);
                    }
        }
        __syncwarp();
        {
            float* ob = out + (size_t)(b0 + 16 * wn) * n_rules + r0 + 32 * wm + lane;
            const float* sr = stg + lane;
#pragma unroll 4
            for (int b = 0; b < 16; ++b) {
                ob[(size_t)b * n_rules] = sr[b * STG_STRIDE];
            }
        }
        __syncwarp();

        __syncthreads();   // buf(par) reads done; next build complete
        par ^= 1;
    }
}

extern "C" void kernel_launch(void* const* d_in, const int* in_sizes, int n_in,
                              void* d_out, int out_size) {
    const float* x  = (const float*)d_in[0];
    const int*   mf = (const int*)d_in[1];
    float* out = (float*)d_out;

    const int n_rules = in_sizes[1] / 8;      // 2048

    cudaFuncSetAttribute(fire_kernel, cudaFuncAttributeMaxDynamicSharedMemorySize, SMEM_TOTAL);
    fire_kernel<<<NBLK, THREADS, SMEM_TOTAL>>>(x, mf, out, n_rules);
}